// round 17
// baseline (speedup 1.0000x reference)
#include <cuda_runtime.h>
#include <math.h>

// Problem constants
#define BB   32
#define SS   1024
#define DD   3
#define NF   512
#define NS   64
#define HID  100
#define FSZ  256

// Decomposition (single-pass scan)
#define NSC  32           // S chunks
#define SCH  (SS/NSC)     // 32 steps per chunk

// Scratch (device globals: allocation-free per harness rules)
__device__ float g_Womg[NF*3];
__device__ float g_totC[BB*NSC*NF];
__device__ float g_totS[BB*NSC*NF];
__device__ int   g_flag[BB*NSC];     // chunk-total ready flags (cleared by k_mlp)

// Warp-wide float add reduction (SHFL butterfly; redux.f32 unavailable on
// the compute_103 PTX target).
__device__ __forceinline__ float warp_sum(float v) {
    #pragma unroll
    for (int o = 16; o; o >>= 1) v += __shfl_xor_sync(0xffffffffu, v, o);
    return v;
}

// ---------------- Fused Fourier-feature MLP ----------------
// Frozen compute path (measured 9.5us best). Block 0 additionally clears the
// scan flags so each graph replay starts from a clean state.

#define APAD 260   // row stride of s_accp: %32==4 -> combine reads hit
                   // distinct banks; %4==0 -> float4 stores stay aligned

__global__ void __launch_bounds__(512) k_mlp(const float* __restrict__ noise,
                                             const float* __restrict__ W1,
                                             const float* __restrict__ b1,
                                             const float* __restrict__ W2,
                                             const float* __restrict__ b2,
                                             const float* __restrict__ W) {
    int f = blockIdx.x;
    int t = threadIdx.x;
    int tl   = t & 255;      // hidden-unit id
    int half = t >> 8;       // 0 or 1: which k half (hidden phase)

    // clear scan flags for this replay (BB*NSC = 1024 = 2*512)
    if (f == 0) { g_flag[t] = 0; g_flag[512 + t] = 0; }

    __shared__ float s_noise[NS];
    __shared__ float s_hp[2][HID];     // hidden k-partials
    __shared__ float s_h[HID];
    __shared__ float s_accp[8*APAD];   // fourier j-group partials
    __shared__ float s_red[8][3];

    if (t < NS) s_noise[t] = noise[f*NS + t];
    __syncthreads();

    // hidden partials: h[j] over k in [half*32, half*32+32), fully unrolled
    if (tl < HID) {
        int k0 = half * 32;
        float a0 = 0.f, a1 = 0.f;
        #pragma unroll
        for (int k = 0; k < 32; k += 2) {
            a0 = fmaf(s_noise[k0+k],   W1[(k0+k)*HID + tl],   a0);
            a1 = fmaf(s_noise[k0+k+1], W1[(k0+k+1)*HID + tl], a1);
        }
        s_hp[half][tl] = a0 + a1;
    }
    __syncthreads();
    if (t < HID)
        s_h[t] = tanhf(b1[t] + s_hp[0][t] + s_hp[1][t]);
    __syncthreads();

    // fourier: thread -> (column quad q4, j-group g); constant 13-trip
    // fully-unrolled loop, overhang clamped+zeroed.
    {
        int q4 = (t & 63) * 4;
        int g  = t >> 6;                 // 0..7
        int j0 = g * 13;
        float ax = 0.f, ay = 0.f, az = 0.f, aw = 0.f;
        #pragma unroll
        for (int jj = 0; jj < 13; jj++) {
            int j  = j0 + jj;
            int jc = (j < HID) ? j : (HID-1);
            float4 w = *reinterpret_cast<const float4*>(
                           W2 + (size_t)jc*FSZ + q4);
            float h = (j < HID) ? s_h[j] : 0.f;
            ax = fmaf(h, w.x, ax);
            ay = fmaf(h, w.y, ay);
            az = fmaf(h, w.z, az);
            aw = fmaf(h, w.w, aw);
        }
        float4 o; o.x = ax; o.y = ay; o.z = az; o.w = aw;
        *reinterpret_cast<float4*>(&s_accp[g*APAD + q4]) = o;
    }
    __syncthreads();

    // combine 8 j-groups per column, tanh, Womg reduction (warps 0..7)
    if (t < 256) {
        float a = 0.f;
        #pragma unroll
        for (int g = 0; g < 8; g++) a += s_accp[g*APAD + t];
        float fs = tanhf(b2[t] + a);
        float p0 = fs * W[t*3+0];
        float p1 = fs * W[t*3+1];
        float p2 = fs * W[t*3+2];
        p0 = warp_sum(p0); p1 = warp_sum(p1); p2 = warp_sum(p2);
        int lane = t & 31, warp = t >> 5;
        if (lane == 0) {
            s_red[warp][0] = p0; s_red[warp][1] = p1; s_red[warp][2] = p2;
        }
    }
    __syncthreads();
    if (t < 3) {
        float v = 0.f;
        #pragma unroll
        for (int w = 0; w < 8; w++) v += s_red[w][t];
        g_Womg[f*3 + t] = v;
    }
}

// ---------------- Single-pass scan: totals + contributions + output ----------
// Each block (sc, b): computes its chunk's sincos ONCE into register arrays,
// publishes chunk totals with a release flag, lookback-waits on predecessor
// chunks (lower blockIdx.x => launched earlier: deadlock-free by induction),
// then replays cached C/S through the exclusive-prefix recurrence and writes
// lam + loglik. Eliminates the entire duplicated sincos pass.

#define RPAD 129   // row stride of s_red (odd => conflict-free strided reads)

__global__ void __launch_bounds__(512) k_scan(const float* __restrict__ X,
                                              const float* __restrict__ alpha,
                                              float* __restrict__ out) {
    int t  = threadIdx.x;            // n = t
    int sc = blockIdx.x, b = blockIdx.y;
    float w0 = g_Womg[t*3+0], w1 = g_Womg[t*3+1], w2 = g_Womg[t*3+2];

    __shared__ float sx[SCH*3];
    __shared__ float s_red[SCH*RPAD];  // [SCH][129]
    int s0 = sc*SCH;
    const float* xp = X + ((size_t)b*SS + s0)*3;
    if (t < SCH*3) sx[t] = xp[t];
    __syncthreads();

    // Phase 1: trig once, cached in registers (fully unrolled => no spill)
    float C[SCH], S[SCH];
    float sumC = 0.f, sumS = 0.f;
    #pragma unroll
    for (int k = 0; k < SCH; k++) {
        float th = fmaf(sx[k*3+2], w2, fmaf(sx[k*3+1], w1, sx[k*3]*w0));
        float sv, cv;
        __sincosf(th, &sv, &cv);
        C[k] = cv; S[k] = sv;
        sumC += cv; sumS += sv;
    }
    int slot = b*NSC + sc;
    g_totC[(size_t)slot*NF + t] = sumC;
    g_totS[(size_t)slot*NF + t] = sumS;
    __syncthreads();                  // all totals of this block written
    if (t == 0) {
        __threadfence();              // release
        atomicExch(&g_flag[slot], 1);
    }

    // Phase 2: lookback — wait for all predecessor chunks of this batch row
    if (sc > 0) {
        if (t == 0) {
            for (int p = 0; p < sc; p++)
                while (atomicAdd(&g_flag[b*NSC + p], 0) == 0) { }
        }
        __syncthreads();
        __threadfence();              // acquire side
    }

    float runC = 0.f, runS = 0.f;
    {
        const float* tc = g_totC + (size_t)(b*NSC)*NF + t;
        const float* ts = g_totS + (size_t)(b*NSC)*NF + t;
        int p = 0;
        for (; p + 4 <= sc; p += 4) {   // 4 independent load pairs in flight
            float c0 = tc[(p+0)*NF], c1 = tc[(p+1)*NF];
            float c2 = tc[(p+2)*NF], c3 = tc[(p+3)*NF];
            float s0_ = ts[(p+0)*NF], s1_ = ts[(p+1)*NF];
            float s2_ = ts[(p+2)*NF], s3_ = ts[(p+3)*NF];
            runC += (c0 + c1) + (c2 + c3);
            runS += (s0_ + s1_) + (s2_ + s3_);
        }
        for (; p < sc; p++) { runC += tc[p*NF]; runS += ts[p*NF]; }
    }

    // Phase 3: contributions from cached trig + short butterfly
    int lane = t & 31, warp = t >> 5;
    int g8   = lane & 7;
    int wr   = warp*8 + g8;           // partial column 0..127
    #pragma unroll
    for (int k = 0; k < SCH; k++) {
        float contrib = C[k]*runC + S[k]*runS;   // EXCLUSIVE prefix
        runC += C[k]; runS += S[k];
        contrib += __shfl_xor_sync(0xffffffffu, contrib, 16);
        contrib += __shfl_xor_sync(0xffffffffu, contrib, 8);
        if (lane < 8) s_red[k*RPAD + wr] = contrib;
    }
    __syncthreads();

    // Tail: 16 threads per k (t>>4 = k, t&15 = j) sum 8 strided partials,
    // then 4-level shfl within the 16-thread group.
    {
        int k = t >> 4, j = t & 15;
        const float* row = s_red + k*RPAD;
        float s = 0.f;
        #pragma unroll
        for (int i = 0; i < 8; i++) s += row[j + 16*i];
        s += __shfl_xor_sync(0xffffffffu, s, 8);
        s += __shfl_xor_sync(0xffffffffu, s, 4);
        s += __shfl_xor_sync(0xffffffffu, s, 2);
        s += __shfl_xor_sync(0xffffffffu, s, 1);
        if (j == 0) {
            float lam = fmaf(alpha[0], s * (1.0f/NF), 10.0f);
            int sg = s0 + k;
            out[b*SS + sg] = lam;
            float x0 = sx[k*3];
            float mask = (x0 > 0.f) ? 1.f : 0.f;
            const float C2 = -3947.8417604357433f;   // -MU*T*(2*pi)^(D-1)
            out[BB*SS + b*(SS+1) + sg] = logf(lam)*mask + C2;
        }
    }
    if (sc == 0 && t == 0) {
        const float C2 = -3947.8417604357433f;
        out[BB*SS + b*(SS+1) + SS] = C2;         // extra (S+1)-th column
    }
}

// ---------------- Launch ----------------

extern "C" void kernel_launch(void* const* d_in, const int* in_sizes, int n_in,
                              void* d_out, int out_size) {
    const float* X     = (const float*)d_in[0];
    const float* noise = (const float*)d_in[1];
    const float* W1    = (const float*)d_in[2];
    const float* b1    = (const float*)d_in[3];
    const float* W2    = (const float*)d_in[4];
    const float* b2    = (const float*)d_in[5];
    const float* W     = (const float*)d_in[6];
    const float* alpha = (const float*)d_in[7];
    float* out = (float*)d_out;

    k_mlp<<<NF, 512>>>(noise, W1, b1, W2, b2, W);

    dim3 grid(NSC, BB);
    k_scan<<<grid, 512>>>(X, alpha, out);
}